// round 7
// baseline (speedup 1.0000x reference)
#include <cuda_runtime.h>
#include <math.h>
#include <stdint.h>

#define Bb 32
#define Tt 64
#define Ee 512
#define Hh 1024
#define VTv 32000
#define HB (Hh*Bb)          // 32768
#define G4 (4*Hh)           // 4096
#define G4B (G4*Bb)
#define NBLK 128
#define NTHR 512
#define BIGK (1<<30)

typedef unsigned long long u64;

__device__ __forceinline__ u64 pk2(float x, float y) {
    u64 r; asm("mov.b64 %0,{%1,%2};" : "=l"(r) : "f"(x), "f"(y)); return r;
}
__device__ __forceinline__ void fma2(u64 &d, u64 a, u64 b) {
    asm("fma.rn.f32x2 %0,%1,%2,%0;" : "+l"(d) : "l"(a), "l"(b));
}
__device__ __forceinline__ float2 up2(u64 v) {
    float2 f; asm("mov.b64 {%0,%1},%2;" : "=f"(f.x), "=f"(f.y) : "l"(v)); return f;
}
__device__ __forceinline__ float sigf(float x) { return 1.f/(1.f+expf(-x)); }

__device__ __forceinline__ uint32_t s2u(const void* p) {
    uint32_t a;
    asm("{ .reg .u64 t; cvta.to.shared.u64 t, %1; cvt.u32.u64 %0, t; }" : "=r"(a) : "l"(p));
    return a;
}
__device__ __forceinline__ void mb_init(uint32_t mbar, uint32_t cnt) {
    asm volatile("mbarrier.init.shared.b64 [%0], %1;" :: "r"(mbar), "r"(cnt) : "memory");
}
__device__ __forceinline__ void mb_expect(uint32_t mbar, uint32_t bytes) {
    asm volatile("mbarrier.arrive.expect_tx.shared.b64 _, [%0], %1;" :: "r"(mbar), "r"(bytes) : "memory");
}
__device__ __forceinline__ void mb_wait(uint32_t mbar, int parity) {
    uint32_t done;
    do {
        asm volatile(
            "{\n\t.reg .pred p;\n\t"
            "mbarrier.try_wait.parity.acquire.cta.shared::cta.b64 p, [%1], %2;\n\t"
            "selp.b32 %0,1,0,p;\n\t}"
            : "=r"(done) : "r"(mbar), "r"((uint32_t)parity) : "memory");
    } while (!done);
}
__device__ __forceinline__ void bulk_g2s(uint32_t dst, const void* src, uint32_t bytes, uint32_t mbar) {
    asm volatile(
        "cp.async.bulk.shared::cluster.global.mbarrier::complete_tx::bytes [%0], [%1], %2, [%3];"
        :: "r"(dst), "l"(src), "r"(bytes), "r"(mbar) : "memory");
}

// ---------------- scratch ----------------
__device__ __align__(16) float g_srcX[Tt*HB];   // phase0: x-proj; phase1: h0e chain
__device__ __align__(16) float g_tgtX[Tt*HB];   // phase0: x-proj; phase1: h0d chain
__device__ __align__(16) float g_encHs[Tt*HB];
__device__ __align__(16) float g_h1d[2*HB];
__device__ __align__(16) float g_c0e[HB];
__device__ __align__(16) float g_c1e[HB];
__device__ __align__(16) float g_c0d[HB];
__device__ __align__(16) float g_c1d[HB];
__device__ __align__(16) float g_zero[HB];
__device__ __align__(16) float g_scoresT[Tt*Bb];
__device__ __align__(16) float g_ctxT[HB];
__device__ __align__(16) float g_wcPart[6*HB];
__device__ __align__(16) float g_htT[HB];
__device__ __align__(16) float g_oePart[8*Ee*Bb];
__device__ __align__(16) float g_outembT[Ee*Tt*Bb];   // [512][2048]
__device__ __align__(16) float g_Wre[2*2*Hh*G4];      // tiled [l][128ct][2048k][32c]
__device__ __align__(16) float g_Wrd[2*2*Hh*G4];
__device__ __align__(16) float g_Wct[32*2*Hh*32];     // [32ct][2048k][32c]
__device__ __align__(16) float g_pjt[16*Hh*32];       // [16ct][1024k][32c]
__device__ __align__(16) float g_bre[2*G4];
__device__ __align__(16) float g_brd[2*G4];
__device__ __align__(16) float g_zxe[Tt*G4B];
__device__ __align__(16) float g_zxd[Tt*G4B];
__device__ __align__(16) float g_elog[(size_t)Tt*Bb*VTv];
__device__ unsigned g_bar;

// dynamic smem layout:
#define WBUF_OFF 0          // 4 x 16384
#define ABUF_OFF 65536      // 4 x 16384
#define RED_OFF  131072     // 8*32*33*4 = 33792
#define ATT_OFF  164864     // 64*33*4 = 8448
#define MBW_OFF  173312     // 4 x 8
#define MBA_OFF  173344     // 4 x 8
#define SMEM_TOT 173376

// ---------------- prep: weight tiling + bias reorder + state zero ------------
__global__ void prep(const float* __restrict__ encW, const float* __restrict__ encb,
                     const float* __restrict__ decW, const float* __restrict__ decb,
                     const float* __restrict__ Wc,   const float* __restrict__ pW) {
    int sec = blockIdx.y;
    long t0 = (long)blockIdx.x*blockDim.x + threadIdx.x;
    long stride = (long)gridDim.x*blockDim.x;
    if (sec < 2) {
        const float* W = sec ? decW : encW;
        float* dst = sec ? g_Wrd : g_Wre;
        long total = 2L*2048*4096;
        for (long i = t0; i < total; i += stride) {
            int c = (int)(i & 31);
            long r = i >> 5;
            int k = (int)(r & 2047); r >>= 11;
            int ct = (int)(r & 127);
            int l = (int)(r >> 7);
            int col = ct*32 + c;
            int n = col >> 2, g = col & 3;
            dst[i] = W[((long)(l*2048 + k))*4096 + g*1024 + n];
        }
    } else if (sec == 2) {
        for (long i = t0; i < 2048L*1024; i += stride) {
            int c = (int)(i & 31); long r = i >> 5;
            int k = (int)(r & 2047); int ct = (int)(r >> 11);
            g_Wct[i] = Wc[(long)k*1024 + ct*32 + c];
        }
        for (long i = t0; i < 1024L*512; i += stride) {
            int c = (int)(i & 31); long r = i >> 5;
            int k = (int)(r & 1023); int ct = (int)(r >> 10);
            g_pjt[i] = pW[(long)k*512 + ct*32 + c];
        }
    } else {
        for (long i = t0; i < 2*G4; i += stride) {
            int l = (int)(i >> 12), col = (int)(i & 4095), n = col>>2, g = col&3;
            g_bre[i] = encb[(l<<12) + g*Hh + n];
            g_brd[i] = decb[(l<<12) + g*Hh + n];
        }
        for (long i = t0; i < HB; i += stride) {
            g_zero[i]=0.f; g_c0e[i]=0.f; g_c1e[i]=0.f; g_c0d[i]=0.f; g_c1d[i]=0.f;
            g_h1d[i]=0.f; g_h1d[i+HB]=0.f;
        }
        if (t0 == 0) g_bar = 0u;
    }
}

// ---------------- fused embedding + input projection (z: 0=src 1=tgt) -------
__global__ void embed2(const int* __restrict__ src, const int* __restrict__ tgt,
                       const float* __restrict__ s_emb, const float* __restrict__ t_emb,
                       const float4* __restrict__ sW, const float4* __restrict__ sB,
                       const float4* __restrict__ tW, const float4* __restrict__ tB) {
    int z = blockIdx.z;
    const int* tok = z ? tgt : src;
    const float* emb = z ? t_emb : s_emb;
    const float4* W4 = z ? tW : sW;
    const float4* b4 = z ? tB : sB;
    float* outX = z ? g_tgtX : g_srcX;
    int t = blockIdx.y;
    int w = threadIdx.x >> 5, lane = threadIdx.x & 31;
    int n4 = blockIdx.x * 8 + w;
    const float* ar = emb + (long)tok[lane*Tt + t] * Ee;
    float4 acc = b4[n4];
    #pragma unroll 4
    for (int k = 0; k < Ee; k++) {
        float a = ar[k];
        float4 wv = W4[k*(Hh/4) + n4];
        acc.x += a*wv.x; acc.y += a*wv.y; acc.z += a*wv.z; acc.w += a*wv.w;
    }
    float* o = outX + (long)t*HB + (n4*4)*Bb + lane;
    o[0]=acc.x; o[32]=acc.y; o[64]=acc.z; o[96]=acc.w;
}

// ---------------- deep-pipelined TMA tile GEMM ----------------
struct Pipe { uint32_t phW, phA; unsigned base; int preW, preA; };

__device__ __forceinline__ void issW(uint32_t smb, int slot, const float* src) {
    uint32_t mb = smb + MBW_OFF + slot*8;
    mb_expect(mb, 16384);
    bulk_g2s(smb + WBUF_OFF + slot*16384, src, 16384, mb);
}
__device__ __forceinline__ void issA(uint32_t smb, int slot, const float* src) {
    uint32_t mb = smb + MBA_OFF + slot*8;
    mb_expect(mb, 16384);
    bulk_g2s(smb + ABUF_OFF + slot*16384, src, 16384, mb);
}

// Computes partials into red[8][32][33] for 32 output cols (block's coltile),
// K region [kbeg, kbeg+nt*128) of A; W pre-offset to kbeg. Prefetches up to 3
// tiles ahead, spilling into the NEXT stage descriptor (W always; A if nAok).
__device__ __forceinline__ void stage_run(
    Pipe& P, char* sm, uint32_t smb,
    const float* XA, const float* XB, int K1, int kbeg, const float* Wt, int nt,
    const float* nXA, const float* nXB, int nK1, int nkbeg, const float* nWt,
    int nnt, bool nAok, float* red)
{
    int tid = threadIdx.x, lane = tid & 31, wid = tid >> 5;
    int cg = wid >> 3, ks = wid & 7;
    u64 acc[8] = {};
    int iW = P.preW, iA = P.preA;
    int nW = 0, nA = 0;
    for (int it = 0; it < nt; it++) {
        int lim = it + 3;
        for (; iW < nt && iW <= lim; iW++)
            if (tid == 0) issW(smb, (int)((P.base + iW) & 3), Wt + (long)iW*(128*32));
        for (; iA < nt && iA <= lim; iA++)
            if (tid == 0) {
                int k = kbeg + iA*128;
                const float* s = (k < K1) ? XA + (long)k*32 : XB + (long)(k-K1)*32;
                issA(smb, (int)((P.base + iA) & 3), s);
            }
        if (iW == nt)
            for (; nW < nnt && nt + nW <= lim; nW++)
                if (tid == 0) issW(smb, (int)((P.base + nt + nW) & 3), nWt + (long)nW*(128*32));
        if (nAok && iA == nt)
            for (; nA < nnt && nt + nA <= lim; nA++)
                if (tid == 0) {
                    int k = nkbeg + nA*128;
                    const float* s = (k < nK1) ? nXA + (long)k*32 : nXB + (long)(k-nK1)*32;
                    issA(smb, (int)((P.base + nt + nA) & 3), s);
                }
        int slot = (int)((P.base + it) & 3);
        mb_wait(smb + MBA_OFF + slot*8, (P.phA >> slot) & 1); P.phA ^= 1u << slot;
        mb_wait(smb + MBW_OFF + slot*8, (P.phW >> slot) & 1); P.phW ^= 1u << slot;
        const float* Ab = (const float*)(sm + ABUF_OFF + slot*16384);
        const float* Wb = (const float*)(sm + WBUF_OFF + slot*16384);
        const float* Ar = Ab + (ks*16)*32;
        const float* Wr = Wb + (ks*16)*32 + cg*16;
        #pragma unroll
        for (int kk = 0; kk < 16; kk++) {
            float a = Ar[kk*32 + lane];
            u64 aa = pk2(a, a);
            const ulonglong2* wq = (const ulonglong2*)(Wr + kk*32);
            ulonglong2 w0 = wq[0], w1 = wq[1], w2 = wq[2], w3 = wq[3];
            fma2(acc[0], aa, w0.x); fma2(acc[1], aa, w0.y);
            fma2(acc[2], aa, w1.x); fma2(acc[3], aa, w1.y);
            fma2(acc[4], aa, w2.x); fma2(acc[5], aa, w2.y);
            fma2(acc[6], aa, w3.x); fma2(acc[7], aa, w3.y);
        }
        __syncthreads();
    }
    P.base += nt; P.preW = nW; P.preA = nA;
    #pragma unroll
    for (int a = 0; a < 8; a++) {
        float2 v = up2(acc[a]);
        red[(ks*32 + cg*16 + 2*a)*33 + lane]     = v.x;
        red[(ks*32 + cg*16 + 2*a + 1)*33 + lane] = v.y;
    }
    __syncthreads();
}

// reduce 8 ksplits + LSTM cell; block covers n = bid*8..+8
__device__ __forceinline__ void lstm_epi(const float* red, const float* __restrict__ b4,
                                         const float* __restrict__ zx,
                                         float* __restrict__ c, float* __restrict__ h,
                                         int bid) {
    int tid = threadIdx.x, lane = tid & 31, w = tid >> 5;
    if (w < 8) {
        int n = bid*8 + w;
        float zi=0.f, zj=0.f, zf=0.f, zo=0.f;
        #pragma unroll
        for (int s = 0; s < 8; s++) {
            const float* r = red + (s*32 + w*4)*33 + lane;
            zi += r[0]; zj += r[33]; zf += r[66]; zo += r[99];
        }
        const float* bb = b4 + n*4;
        zi += bb[0]; zj += bb[1]; zf += bb[2]; zo += bb[3];
        if (zx) {
            const float* z = zx + n*128 + lane;
            zi += z[0]; zj += z[32]; zf += z[64]; zo += z[96];
        }
        int idx = n*Bb + lane;
        float cn = c[idx]*sigf(zf + 1.f) + sigf(zi)*tanhf(zj);
        c[idx] = cn;
        h[idx] = tanhf(cn)*sigf(zo);
    }
    __syncthreads();
}

__device__ __forceinline__ void part_epi(const float* red, float* __restrict__ dst) {
    for (int i = threadIdx.x; i < 32*32; i += NTHR) {
        int cl = i >> 5, b = i & 31;
        float s = 0.f;
        #pragma unroll
        for (int sl = 0; sl < 8; sl++) s += red[(sl*32 + cl)*33 + b];
        dst[cl*32 + b] = s;
    }
}

// ---------------- xgate precompute ----------------
__global__ void __launch_bounds__(NTHR) xgate(const float* __restrict__ X,
                                              const float* __restrict__ Wtiled,
                                              float* __restrict__ out) {
    extern __shared__ __align__(16) char dynsmem[];
    uint32_t smb = s2u(dynsmem);
    float* red = (float*)(dynsmem + RED_OFF);
    if (threadIdx.x == 0) {
        #pragma unroll
        for (int j = 0; j < 4; j++) { mb_init(smb + MBW_OFF + j*8, 1); mb_init(smb + MBA_OFF + j*8, 1); }
        asm volatile("fence.proxy.async.shared::cta;" ::: "memory");
    }
    __syncthreads();
    Pipe P{0,0,0,0,0};
    int t = blockIdx.y, ct = blockIdx.x;
    stage_run(P, dynsmem, smb, X + (long)t*HB, X, BIGK, 0,
              Wtiled + (long)ct*(2048*32), 8,
              nullptr, nullptr, BIGK, 0, nullptr, 0, false, red);
    part_epi(red, out + (long)t*G4B + ct*1024);
}

// ---------------- grid barrier ----------------
__device__ __forceinline__ void gbar(unsigned &tgt) {
    tgt += NBLK;
    __syncthreads();
    if (threadIdx.x == 0) {
        __threadfence();
        atomicAdd(&g_bar, 1u);
        unsigned v;
        do {
            asm volatile("ld.acquire.gpu.u32 %0,[%1];" : "=r"(v) : "l"(&g_bar) : "memory");
        } while (v < tgt);
    }
    __syncthreads();
}

// ---------------- persistent sequence kernel ----------------
__global__ void __launch_bounds__(NTHR,1) seq_kernel(const float* __restrict__ b_c,
                                                     const float* __restrict__ proj_b) {
    extern __shared__ __align__(16) char dynsmem[];
    uint32_t smb = s2u(dynsmem);
    float* red = (float*)(dynsmem + RED_OFF);
    float* attw = (float*)(dynsmem + ATT_OFF);
    int tid = threadIdx.x, lane = tid & 31, wid = tid >> 5, bid = blockIdx.x;
    unsigned tgt = 0;
    if (tid == 0) {
        #pragma unroll
        for (int j = 0; j < 4; j++) { mb_init(smb + MBW_OFF + j*8, 1); mb_init(smb + MBA_OFF + j*8, 1); }
        asm volatile("fence.proxy.async.shared::cta;" ::: "memory");
    }
    __syncthreads();
    Pipe P{0,0,0,0,0};

    const float* We0h = g_Wre + ((long)bid*2048 + 1024)*32;
    const float* We1  = g_Wre + ((long)(128 + bid)*2048)*32;
    const float* Wd0h = g_Wrd + ((long)bid*2048 + 1024)*32;
    const float* Wd1  = g_Wrd + ((long)(128 + bid)*2048)*32;
    const float* be0 = g_bre;
    const float* be1 = g_bre + G4;
    const float* bd0 = g_brd;
    const float* bd1 = g_brd + G4;
    // phase-2 per-block stage geometry
    int bb2 = bid - 64;
    int ct2 = (bb2 >= 0) ? (bb2 >> 1) : 0, ksg2 = bb2 & 1;
    const float* Wc2 = g_Wct + ((long)ct2*2048 + ksg2*512)*32;
    int ct4 = bid >> 2, ksg4 = bid & 3;
    const float* Wc4 = g_Wct + ((long)ct4*2048 + 1024 + ksg4*256)*32;
    int ct6 = bid >> 3, ksg6 = bid & 7;
    const float* Wp6 = g_pjt + ((long)ct6*1024 + ksg6*128)*32;

    // ---- phase 1 ----
    for (int t = 0; t < Tt; t++) {
        const float* h0ep = t ? (g_srcX + (long)(t-1)*HB) : g_zero;
        const float* h0dp = t ? (g_tgtX + (long)(t-1)*HB) : g_zero;
        const float* h1p  = t ? (g_encHs + (long)(t-1)*HB) : g_zero;
        // E0 (next = D0, A ready)
        stage_run(P, dynsmem, smb, h0ep, h0ep, BIGK, 0, We0h, 8,
                  h0dp, h0dp, BIGK, 0, Wd0h, 8, true, red);
        lstm_epi(red, be0, g_zxe + (long)t*G4B, g_c0e, g_srcX + (long)t*HB, bid);
        // D0 (next = E1, A NOT ready: W only)
        stage_run(P, dynsmem, smb, h0dp, h0dp, BIGK, 0, Wd0h, 8,
                  g_srcX + (long)t*HB, h1p, 1024, 0, We1, 16, false, red);
        lstm_epi(red, bd0, g_zxd + (long)t*G4B, g_c0d, g_tgtX + (long)t*HB, bid);
        gbar(tgt);
        // E1 (next = E0(t+1) or phase2 S1(0); A ready in both cases)
        if (t < Tt-1) {
            stage_run(P, dynsmem, smb, g_srcX + (long)t*HB, h1p, 1024, 0, We1, 16,
                      g_srcX + (long)t*HB, g_srcX + (long)t*HB, BIGK, 0, We0h, 8, true, red);
        } else {
            stage_run(P, dynsmem, smb, g_srcX + (long)t*HB, h1p, 1024, 0, We1, 16,
                      g_tgtX, g_h1d, 1024, 0, Wd1, 16, true, red);
        }
        lstm_epi(red, be1, nullptr, g_c1e, g_encHs + (long)t*HB, bid);
        gbar(tgt);
    }

    // ---- phase 2 ----
    for (int t = 0; t < Tt; t++) {
        int p = t & 1;
        const float* h1prev = g_h1d + p*HB;
        float* h1cur = g_h1d + (1-p)*HB;

        // S1: dec layer1 (K=2048). next: blocks>=64 -> S2 stage; blocks<64 -> S4. A not ready.
        if (bid >= 64)
            stage_run(P, dynsmem, smb, g_tgtX + (long)t*HB, h1prev, 1024, 0, Wd1, 16,
                      h1cur, h1cur, BIGK, ksg2*512, Wc2, 4, false, red);
        else
            stage_run(P, dynsmem, smb, g_tgtX + (long)t*HB, h1prev, 1024, 0, Wd1, 16,
                      g_ctxT, g_ctxT, BIGK, ksg4*256, Wc4, 2, false, red);
        lstm_epi(red, bd1, nullptr, g_c1d, h1cur, bid);
        gbar(tgt);

        // S2: scores (blocks 0-63) || W_c h-part stage (blocks 64-127)
        if (bid < Tt) {
            const float* e = g_encHs + (long)bid*HB;
            float s = 0.f;
            #pragma unroll 4
            for (int hh = wid*64; hh < wid*64 + 64; hh++)
                s += h1cur[hh*Bb + lane] * e[hh*Bb + lane];
            attw[wid*33 + lane] = s;
            __syncthreads();
            if (wid == 0) {
                float a = 0.f;
                #pragma unroll
                for (int j = 0; j < 16; j++) a += attw[j*33 + lane];
                g_scoresT[bid*Bb + lane] = a;
            }
            __syncthreads();
        } else {
            stage_run(P, dynsmem, smb, h1cur, h1cur, BIGK, ksg2*512, Wc2, 4,
                      g_ctxT, g_ctxT, BIGK, ksg4*256, Wc4, 2, false, red);
            part_epi(red, g_wcPart + (long)ksg2*HB + ct2*1024);
        }
        gbar(tgt);

        // S3: softmax (warp 0, redundant per block) + ctx
        if (wid == 0) {
            float mx = -1e30f;
            #pragma unroll
            for (int q = 0; q < Tt; q++) mx = fmaxf(mx, g_scoresT[q*Bb + lane]);
            float sum = 0.f;
            #pragma unroll
            for (int q = 0; q < Tt; q++) {
                float e = expf(g_scoresT[q*Bb + lane] - mx);
                attw[q*33 + lane] = e; sum += e;
            }
            float inv = 1.f/sum;
            #pragma unroll
            for (int q = 0; q < Tt; q++) attw[q*33 + lane] *= inv;
        }
        __syncthreads();
        if (wid < 8) {
            int hh = bid*8 + wid;
            float s = 0.f;
            #pragma unroll 8
            for (int q = 0; q < Tt; q++)
                s += attw[q*33 + lane] * g_encHs[((long)q*Hh + hh)*Bb + lane];
            g_ctxT[hh*Bb + lane] = s;
        }
        gbar(tgt);

        // S4: W_c ctx-part. next = S6 (W only; htT not ready).
        stage_run(P, dynsmem, smb, g_ctxT, g_ctxT, BIGK, ksg4*256, Wc4, 2,
                  g_htT, g_htT, BIGK, ksg6*128, Wp6, 1, false, red);
        part_epi(red, g_wcPart + (long)(2 + ksg4)*HB + ct4*1024);
        gbar(tgt);

        // S5: reduce -> htT
        if (bid < 64) {
            int id = bid*NTHR + tid;
            int n = id >> 5;
            float s = b_c[n];
            #pragma unroll
            for (int sl = 0; sl < 6; sl++) s += g_wcPart[(long)sl*HB + id];
            g_htT[id] = s;
        }
        gbar(tgt);

        // S6: proj. next = S1(t+1) (A ready: h1cur barriered since S1-end).
        if (t < Tt-1)
            stage_run(P, dynsmem, smb, g_htT, g_htT, BIGK, ksg6*128, Wp6, 1,
                      g_tgtX + (long)(t+1)*HB, h1cur, 1024, 0, Wd1, 16, true, red);
        else
            stage_run(P, dynsmem, smb, g_htT, g_htT, BIGK, ksg6*128, Wp6, 1,
                      nullptr, nullptr, BIGK, 0, nullptr, 0, false, red);
        part_epi(red, g_oePart + (long)ksg6*(Ee*Bb) + ct6*1024);
        gbar(tgt);

        // S7: reduce -> outembT [512][2048] (no trailing barrier needed)
        if (bid < 32) {
            int id = bid*NTHR + tid;
            int n = id >> 5, b = id & 31;
            float s = proj_b[n];
            #pragma unroll
            for (int s8 = 0; s8 < 8; s8++) s += g_oePart[(long)s8*(Ee*Bb) + id];
            g_outembT[(long)n*2048 + t*Bb + b] = s;
        }
    }
}

// ---------------- vocab GEMM + exp epilogue ----------------
__global__ void __launch_bounds__(512) gemm_logits(const float* __restrict__ AT,
                                                   const float* __restrict__ Bw,
                                                   const float* __restrict__ bias,
                                                   float* __restrict__ E) {
    __shared__ float As[16][128];
    __shared__ float Bs[16][128];
    int tid = threadIdx.x;
    int bn = blockIdx.x * 128;
    int bm = blockIdx.y * 128;
    int r8 = tid >> 5, c32 = tid & 31;
    int sk = tid >> 5, sq = tid & 31;
    u64 acc[8][2] = {};
    float4 pa = *(const float4*)(AT + (long)sk*2048 + bm + sq*4);
    float4 pb = *(const float4*)(Bw + (long)sk*VTv + bn + sq*4);
    for (int k0 = 0; k0 < 512; k0 += 16) {
        *(float4*)&As[sk][sq*4] = pa;
        *(float4*)&Bs[sk][sq*4] = pb;
        __syncthreads();
        if (k0 + 16 < 512) {
            pa = *(const float4*)(AT + (long)(k0+16+sk)*2048 + bm + sq*4);
            pb = *(const float4*)(Bw + (long)(k0+16+sk)*VTv + bn + sq*4);
        }
        #pragma unroll
        for (int k = 0; k < 16; k++) {
            float4 a0 = *(const float4*)&As[k][r8*8];
            float4 a1 = *(const float4*)&As[k][r8*8 + 4];
            float4 bv = *(const float4*)&Bs[k][c32*4];
            u64 b01 = pk2(bv.x, bv.y), b23 = pk2(bv.z, bv.w);
            u64 aa;
            aa = pk2(a0.x,a0.x); fma2(acc[0][0], aa, b01); fma2(acc[0][1], aa, b23);
            aa = pk2(a0.y,a0.y); fma2(acc[1][0], aa, b01); fma2(acc[1][1], aa, b23);
            aa = pk2(a0.z,a0.z); fma2(acc[2][0], aa, b01); fma2(acc[2][1], aa, b23);
            aa = pk2(a0.w,a0.w); fma2(acc[3][0], aa, b01); fma2(acc[3][1], aa, b23);
            aa = pk2(a1.x,a1.x); fma2(acc[4][0], aa, b01); fma2(acc[4][1], aa, b23);
            aa = pk2(a1.y,a1.y); fma2(acc[5][0], aa, b01); fma2(acc[5][1], aa, b23);
            aa = pk2(a1.z,a1.z); fma2(acc[6][0], aa, b01); fma2(acc[6][1], aa, b23);
            aa = pk2(a1.w,a1.w); fma2(acc[7][0], aa, b01); fma2(acc[7][1], aa, b23);
        }
        __syncthreads();
    }
    float4 bi = *(const float4*)(bias + bn + c32*4);
    #pragma unroll
    for (int j = 0; j < 8; j++) {
        float2 v01 = up2(acc[j][0]), v23 = up2(acc[j][1]);
        float4 o;
        o.x = expf(v01.x + bi.x);
        o.y = expf(v01.y + bi.y);
        o.z = expf(v23.x + bi.z);
        o.w = expf(v23.y + bi.w);
        *(float4*)(E + (size_t)(bm + r8*8 + j)*VTv + bn + c32*4) = o;
    }
}

// ---------------- normalize + layout remap ----------------
__global__ void softmax_norm(const float* __restrict__ E, float* __restrict__ out) {
    int m = blockIdx.x;
    const float* er = E + (size_t)m*VTv;
    int tid = threadIdx.x;
    __shared__ float red[256];
    float sum = 0.f;
    for (int i = tid; i < VTv; i += 256) sum += er[i];
    red[tid] = sum; __syncthreads();
    for (int s = 128; s; s >>= 1) { if (tid < s) red[tid] += red[tid+s]; __syncthreads(); }
    float inv = 1.f/red[0];
    int t = m >> 5, b = m & 31;
    float* orow = out + (size_t)(b*Tt + t)*VTv;
    for (int i = tid; i < VTv; i += 256) orow[i] = er[i]*inv;
}

// ---------------- host ----------------
extern "C" void kernel_launch(void* const* d_in, const int* in_sizes, int n_in,
                              void* d_out, int out_size) {
    const int*   src    = (const int*)d_in[0];
    const int*   tgt    = (const int*)d_in[1];
    const float* s_emb  = (const float*)d_in[2];
    const float* s_pW   = (const float*)d_in[3];
    const float* s_pb   = (const float*)d_in[4];
    const float* t_emb  = (const float*)d_in[5];
    const float* t_pW   = (const float*)d_in[6];
    const float* t_pb   = (const float*)d_in[7];
    const float* enc_W  = (const float*)d_in[8];
    const float* enc_b  = (const float*)d_in[9];
    const float* dec_W  = (const float*)d_in[10];
    const float* dec_b  = (const float*)d_in[11];
    const float* W_c    = (const float*)d_in[12];
    const float* b_c    = (const float*)d_in[13];
    const float* proj_W = (const float*)d_in[14];
    const float* proj_b = (const float*)d_in[15];
    const float* proj_Wo= (const float*)d_in[16];
    const float* proj_bo= (const float*)d_in[17];
    float* out = (float*)d_out;

    float *srcX,*tgtX,*Wre,*Wrd,*zxe,*zxd,*outembT,*elog;
    cudaGetSymbolAddress((void**)&srcX,    g_srcX);
    cudaGetSymbolAddress((void**)&tgtX,    g_tgtX);
    cudaGetSymbolAddress((void**)&Wre,     g_Wre);
    cudaGetSymbolAddress((void**)&Wrd,     g_Wrd);
    cudaGetSymbolAddress((void**)&zxe,     g_zxe);
    cudaGetSymbolAddress((void**)&zxd,     g_zxd);
    cudaGetSymbolAddress((void**)&outembT, g_outembT);
    cudaGetSymbolAddress((void**)&elog,    g_elog);

    cudaFuncSetAttribute(seq_kernel, cudaFuncAttributeMaxDynamicSharedMemorySize, SMEM_TOT);
    cudaFuncSetAttribute(xgate,      cudaFuncAttributeMaxDynamicSharedMemorySize, SMEM_TOT);

    // launch order fixed so that ncu (-s 5) captures seq_kernel
    prep<<<dim3(4096,4), 256>>>(enc_W, enc_b, dec_W, dec_b, W_c, proj_W);
    embed2<<<dim3(32,64,2), 256>>>(src, tgt, s_emb, t_emb,
                                   (const float4*)s_pW, (const float4*)s_pb,
                                   (const float4*)t_pW, (const float4*)t_pb);
    xgate<<<dim3(128,Tt), NTHR, SMEM_TOT>>>(srcX, Wre, zxe);
    xgate<<<dim3(128,Tt), NTHR, SMEM_TOT>>>(tgtX, Wrd, zxd);
    seq_kernel<<<NBLK, NTHR, SMEM_TOT>>>(b_c, proj_b);
    gemm_logits<<<dim3(VTv/128, (Tt*Bb)/128), 512>>>(outembT, proj_Wo, proj_bo, elog);
    softmax_norm<<<Tt*Bb, 256>>>(elog, out);
}